// round 2
// baseline (speedup 1.0000x reference)
#include <cuda_runtime.h>

#define N_NODES 8192
#define IN_DIM  256
#define OUT_DIM 128

// Scratch (device globals — no allocation allowed in kernel_launch)
__device__ float P_buf[N_NODES * OUT_DIM];  // g[j] * Wh[j][c]
__device__ float g_buf[N_NODES];            // exp(e[j])

// ---------------------------------------------------------------------------
// Phase 1: Wh = X @ W^T  (fused: e = relu(Wh)@a_w, g = exp(e), P = g*Wh)
// grid = 128 blocks (64 rows each), block = 256 threads (16x16 tiling)
// ---------------------------------------------------------------------------
__global__ __launch_bounds__(256)
void gat_phase1(const float* __restrict__ X,
                const float* __restrict__ W,
                const float* __restrict__ a_w)
{
    __shared__ float Xs[32][68];    // Xs[k][r] = X[r0+r][k0+k]
    __shared__ float Ws[32][132];   // Ws[k][c] = W[c][k0+k]
    __shared__ float aw_s[OUT_DIM];

    const int t  = threadIdx.x;
    const int tx = t & 15;
    const int ty = t >> 4;
    const int r0 = blockIdx.x * 64;

    if (t < OUT_DIM) aw_s[t] = a_w[t];

    float acc[4][8];
    #pragma unroll
    for (int r = 0; r < 4; r++)
        #pragma unroll
        for (int j = 0; j < 8; j++) acc[r][j] = 0.0f;

    for (int k0 = 0; k0 < IN_DIM; k0 += 32) {
        // load X tile (64 rows x 32 k), float4 global reads, transpose into smem
        {
            const int r = t >> 2, q = t & 3;
            #pragma unroll
            for (int it = 0; it < 2; it++) {
                const int f4 = q + 4 * it;
                float4 v = *reinterpret_cast<const float4*>(
                    &X[(r0 + r) * IN_DIM + k0 + 4 * f4]);
                Xs[4*f4+0][r] = v.x; Xs[4*f4+1][r] = v.y;
                Xs[4*f4+2][r] = v.z; Xs[4*f4+3][r] = v.w;
            }
        }
        // load W tile transposed: Ws[k][c] = W[c][k0+k]
        {
            const int k = t & 31, cb = t >> 5;
            #pragma unroll
            for (int it = 0; it < 16; it++) {
                const int c = cb + 8 * it;
                Ws[k][c] = W[c * IN_DIM + k0 + k];
            }
        }
        __syncthreads();

        #pragma unroll
        for (int k = 0; k < 32; k++) {
            float4 av = *reinterpret_cast<const float4*>(&Xs[k][4 * ty]);
            float ar[4] = {av.x, av.y, av.z, av.w};
            #pragma unroll
            for (int j = 0; j < 8; j++) {
                float b = Ws[k][tx + 16 * j];
                #pragma unroll
                for (int r = 0; r < 4; r++)
                    acc[r][j] = fmaf(ar[r], b, acc[r][j]);
            }
        }
        __syncthreads();
    }

    // Epilogue: e per row (reduce over the 16 tx lanes), g = exp(e), write P & g
    #pragma unroll
    for (int r = 0; r < 4; r++) {
        float ep = 0.0f;
        #pragma unroll
        for (int j = 0; j < 8; j++)
            ep = fmaf(fmaxf(acc[r][j], 0.0f), aw_s[tx + 16 * j], ep);
        // xor-reduce over tx bits (lanes 0..15 within each half-warp share ty)
        #pragma unroll
        for (int m = 8; m >= 1; m >>= 1)
            ep += __shfl_xor_sync(0xffffffffu, ep, m, 32);

        const float g  = expf(ep);
        const int row  = r0 + 4 * ty + r;
        #pragma unroll
        for (int j = 0; j < 8; j++)
            P_buf[row * OUT_DIM + tx + 16 * j] = g * acc[r][j];
        if (tx == 0) g_buf[row] = g;
    }
}

// ---------------------------------------------------------------------------
// Phase 2: h[i] = relu( (A @ P)[i] / (A @ g)[i] )
// M=8192, N=128 (+fused denominator), K=8192
// grid = 128 blocks (64 rows each), block = 256 threads.
// Thread tile: 4 rows x 8 cols, columns handled as 4 f32x2 pairs via
// packed fma.rn.f32x2 (FFMA2) for 2x fp32 FMA throughput.
// Column pairs are strided (pair index = tx + 16*j) so LDS.64 reads are
// conflict-free across the 16 tx lanes.
// ---------------------------------------------------------------------------
__global__ __launch_bounds__(256)
void gat_phase2(const float* __restrict__ A, float* __restrict__ out)
{
    __shared__ float As[32][68];    // As[k][r] = A[r0+r][k0+k]
    __shared__ float Ps[32][132];   // Ps[k][c] = P[k0+k][c]
    __shared__ float gs[32];

    const int t  = threadIdx.x;
    const int tx = t & 15;
    const int ty = t >> 4;
    const int r0 = blockIdx.x * 64;

    unsigned long long acc2[4][4];
    float den[4];
    #pragma unroll
    for (int r = 0; r < 4; r++) {
        den[r] = 0.0f;
        #pragma unroll
        for (int j = 0; j < 4; j++) acc2[r][j] = 0ULL;
    }

    for (int k0 = 0; k0 < N_NODES; k0 += 32) {
        // A tile (64 rows x 32 k): float4 reads, transposed scatter into smem
        {
            const int r = t >> 2, q = t & 3;
            #pragma unroll
            for (int it = 0; it < 2; it++) {
                const int f4 = q + 4 * it;
                float4 v = *reinterpret_cast<const float4*>(
                    &A[(size_t)(r0 + r) * N_NODES + k0 + 4 * f4]);
                As[4*f4+0][r] = v.x; As[4*f4+1][r] = v.y;
                As[4*f4+2][r] = v.z; As[4*f4+3][r] = v.w;
            }
        }
        // P tile (32 k x 128 c): float4 reads, direct float4 smem stores
        {
            const int c4 = t & 31, kb = t >> 5;
            #pragma unroll
            for (int it = 0; it < 4; it++) {
                const int k = kb + 8 * it;
                *reinterpret_cast<float4*>(&Ps[k][4 * c4]) =
                    *reinterpret_cast<const float4*>(&P_buf[(k0 + k) * OUT_DIM + 4 * c4]);
            }
        }
        if (t < 32) gs[t] = g_buf[k0 + t];
        __syncthreads();

        #pragma unroll
        for (int k = 0; k < 32; k++) {
            // 4 A-values for this thread's rows: one broadcast LDS.128
            float4 av = *reinterpret_cast<const float4*>(&As[k][4 * ty]);
            float ar[4] = {av.x, av.y, av.z, av.w};
            const float gk = gs[k];

            unsigned long long a2[4];
            #pragma unroll
            for (int r = 0; r < 4; r++) {
                asm("mov.b64 %0, {%1, %1};"
                    : "=l"(a2[r]) : "r"(__float_as_uint(ar[r])));
                den[r] = fmaf(ar[r], gk, den[r]);
            }

            const unsigned long long* prow =
                reinterpret_cast<const unsigned long long*>(&Ps[k][0]);
            #pragma unroll
            for (int j = 0; j < 4; j++) {
                unsigned long long p2 = prow[tx + 16 * j];   // LDS.64, conflict-free
                #pragma unroll
                for (int r = 0; r < 4; r++)
                    asm("fma.rn.f32x2 %0, %1, %2, %0;"
                        : "+l"(acc2[r][j]) : "l"(a2[r]), "l"(p2));
            }
        }
        __syncthreads();
    }

    // Epilogue: divide by denominator, relu, float2 stores
    #pragma unroll
    for (int r = 0; r < 4; r++) {
        const float inv = 1.0f / den[r];
        const int row = r0 + 4 * ty + r;
        #pragma unroll
        for (int j = 0; j < 4; j++) {
            unsigned lo, hi;
            asm("mov.b64 {%0, %1}, %2;" : "=r"(lo), "=r"(hi) : "l"(acc2[r][j]));
            float2 o;
            o.x = fmaxf(__uint_as_float(lo) * inv, 0.0f);
            o.y = fmaxf(__uint_as_float(hi) * inv, 0.0f);
            *reinterpret_cast<float2*>(&out[row * OUT_DIM + 2 * (tx + 16 * j)]) = o;
        }
    }
}

// ---------------------------------------------------------------------------
extern "C" void kernel_launch(void* const* d_in, const int* in_sizes, int n_in,
                              void* d_out, int out_size)
{
    const float* X   = (const float*)d_in[0];
    const float* A   = (const float*)d_in[1];
    const float* W   = (const float*)d_in[2];
    const float* a_w = (const float*)d_in[3];
    float* out = (float*)d_out;

    gat_phase1<<<N_NODES / 64, 256>>>(X, W, a_w);
    gat_phase2<<<N_NODES / 64, 256>>>(A, out);
}

// round 4
// speedup vs baseline: 2.4536x; 2.4536x over previous
#include <cuda_runtime.h>
#include <cuda_bf16.h>
#include <cstdint>

#define N_NODES 8192
#define IN_DIM  256
#define OUT_DIM 128
#define NCOLS   144     // 128 out cols + g col (128) + 15 pad
#define CH_K    32      // K per chunk (bf16)
#define SPLITS  2

// ---------------- device scratch (zero-initialized at module load) ---------
__device__ __align__(16) __nv_bfloat16 Pt_hi[NCOLS * N_NODES];  // [n][k]
__device__ __align__(16) __nv_bfloat16 Pt_lo[NCOLS * N_NODES];  // [n][k]
__device__ __align__(16) float part_buf[SPLITS * N_NODES * NCOLS];

// ---------------- helpers ---------------------------------------------------
__device__ __forceinline__ uint32_t smem_u32(const void* p) {
    uint32_t a;
    asm("{ .reg .u64 t; cvta.to.shared.u64 t, %1; cvt.u32.u64 %0, t; }"
        : "=r"(a) : "l"(p));
    return a;
}
// XOR-swizzled byte offset inside a [rows][32 bf16] tile (64B rows):
// 16B chunk index permuted by ((row>>1)&3) -> conflict-free ldmatrix & STS.
__device__ __forceinline__ uint32_t swz(int row, int chunk) {
    return (uint32_t)(row * 64 + ((chunk ^ ((row >> 1) & 3)) << 4));
}

#define LDSM_X4(r, addr) \
    asm volatile("ldmatrix.sync.aligned.m8n8.x4.shared.b16 {%0,%1,%2,%3}, [%4];" \
        : "=r"((r)[0]), "=r"((r)[1]), "=r"((r)[2]), "=r"((r)[3]) : "r"(addr))
#define LDSM_X2(r0, r1, addr) \
    asm volatile("ldmatrix.sync.aligned.m8n8.x2.shared.b16 {%0,%1}, [%2];" \
        : "=r"(r0), "=r"(r1) : "r"(addr))
#define MMA16816(c, a, b0, b1) \
    asm volatile("mma.sync.aligned.m16n8k16.row.col.f32.bf16.bf16.f32 " \
        "{%0,%1,%2,%3},{%4,%5,%6,%7},{%8,%9},{%0,%1,%2,%3};" \
        : "+f"((c)[0]), "+f"((c)[1]), "+f"((c)[2]), "+f"((c)[3]) \
        : "r"((a)[0]), "r"((a)[1]), "r"((a)[2]), "r"((a)[3]), "r"(b0), "r"(b1))
#define CP_ASYNC16(daddr, gptr) \
    asm volatile("cp.async.cg.shared.global [%0], [%1], 16;" \
        :: "r"(daddr), "l"(gptr) : "memory")
#define CP_COMMIT() asm volatile("cp.async.commit_group;" ::: "memory")
#define CP_WAIT0()  asm volatile("cp.async.wait_group 0;" ::: "memory")

// ---------------------------------------------------------------------------
// Phase 1: Wh = X @ W^T, e = relu(Wh)@a_w, g = exp(e).
// Writes Pt_hi/Pt_lo[n][j]: n<128 = bf16 hi/lo split of g[j]*Wh[j][n],
// n=128 = hi/lo of g[j]. Rows 129..143 stay zero.
// ---------------------------------------------------------------------------
__global__ __launch_bounds__(256)
void gat_phase1(const float* __restrict__ X,
                const float* __restrict__ W,
                const float* __restrict__ a_w)
{
    __shared__ __align__(16) unsigned char sraw[21504];
    __shared__ float aw_s[OUT_DIM];
    float* Xs = (float*)sraw;             // [32][36]
    float* Ws = (float*)(sraw + 4608);    // [32][132]

    const int t  = threadIdx.x;
    const int tx = t & 15;
    const int ty = t >> 4;
    const int node0 = blockIdx.x * 32;

    if (t < OUT_DIM) aw_s[t] = a_w[t];

    float acc[2][8];
    #pragma unroll
    for (int r = 0; r < 2; r++)
        #pragma unroll
        for (int j = 0; j < 8; j++) acc[r][j] = 0.0f;

    for (int k0 = 0; k0 < IN_DIM; k0 += 32) {
        {   // X tile: 32 rows x 32 k
            const int row = t >> 3, q = t & 7;
            float4 v = *reinterpret_cast<const float4*>(
                &X[(node0 + row) * IN_DIM + k0 + 4 * q]);
            Xs[(4*q+0)*36 + row] = v.x; Xs[(4*q+1)*36 + row] = v.y;
            Xs[(4*q+2)*36 + row] = v.z; Xs[(4*q+3)*36 + row] = v.w;
        }
        {   // W tile transposed
            const int k = t & 31, cb = t >> 5;
            #pragma unroll
            for (int it = 0; it < 16; it++) {
                const int c = cb + 8 * it;
                Ws[k * 132 + c] = W[c * IN_DIM + k0 + k];
            }
        }
        __syncthreads();

        #pragma unroll
        for (int k = 0; k < 32; k++) {
            float2 av = *reinterpret_cast<const float2*>(&Xs[k * 36 + 2 * ty]);
            #pragma unroll
            for (int j = 0; j < 8; j++) {
                float b = Ws[k * 132 + tx + 16 * j];
                acc[0][j] = fmaf(av.x, b, acc[0][j]);
                acc[1][j] = fmaf(av.y, b, acc[1][j]);
            }
        }
        __syncthreads();
    }

    float g[2];
    #pragma unroll
    for (int r = 0; r < 2; r++) {
        float ep = 0.0f;
        #pragma unroll
        for (int j = 0; j < 8; j++)
            ep = fmaf(fmaxf(acc[r][j], 0.0f), aw_s[tx + 16 * j], ep);
        #pragma unroll
        for (int m = 8; m >= 1; m >>= 1)
            ep += __shfl_xor_sync(0xffffffffu, ep, m, 32);
        g[r] = expf(ep);
    }

    // transpose + split through smem, two passes (hi then lo)
    __nv_bfloat16* th = (__nv_bfloat16*)sraw;   // [129][36]
    #pragma unroll
    for (int pass = 0; pass < 2; pass++) {
        __nv_bfloat16* dstbuf = pass ? Pt_lo : Pt_hi;
        #pragma unroll
        for (int j = 0; j < 8; j++) {
            const int c = tx + 16 * j;
            float v0 = g[0] * acc[0][j];
            float v1 = g[1] * acc[1][j];
            __nv_bfloat16 h0 = __float2bfloat16(v0);
            __nv_bfloat16 h1 = __float2bfloat16(v1);
            __nv_bfloat162 o;
            if (pass == 0) o = __halves2bfloat162(h0, h1);
            else o = __halves2bfloat162(
                         __float2bfloat16(v0 - __bfloat162float(h0)),
                         __float2bfloat16(v1 - __bfloat162float(h1)));
            *reinterpret_cast<__nv_bfloat162*>(&th[c * 36 + 2 * ty]) = o;
        }
        if (tx == 0) {  // g column (row 128)
            __nv_bfloat16 h0 = __float2bfloat16(g[0]);
            __nv_bfloat16 h1 = __float2bfloat16(g[1]);
            __nv_bfloat162 o;
            if (pass == 0) o = __halves2bfloat162(h0, h1);
            else o = __halves2bfloat162(
                         __float2bfloat16(g[0] - __bfloat162float(h0)),
                         __float2bfloat16(g[1] - __bfloat162float(h1)));
            *reinterpret_cast<__nv_bfloat162*>(&th[128 * 36 + 2 * ty]) = o;
        }
        __syncthreads();
        {
            const int wid = t >> 5, lid = t & 31;
            const int l = lid & 15;
            for (int c = wid * 2 + (lid >> 4); c < 129; c += 16) {
                unsigned v = *reinterpret_cast<unsigned*>(&th[c * 36 + 2 * l]);
                *reinterpret_cast<unsigned*>(
                    &dstbuf[(size_t)c * N_NODES + node0 + 2 * l]) = v;
            }
        }
        __syncthreads();
    }
}

// ---------------------------------------------------------------------------
// Phase 2: HMMA bf16 GEMM. part[split] = A_bf16[128 x 4096] @ (Pt_hi+Pt_lo)^T
// CTA: M=128, N=144, K-chunk 32; 512 threads = 16 warps (m16 x n72 each).
// 2-stage smem pipeline: A via LDG+cvt+STS (fp32->bf16 exact), B via cp.async.
// ---------------------------------------------------------------------------
#define STG_BYTES 26624     // A 8192 + Bhi 9216 + Blo 9216
#define BH_OFF    8192
#define BL_OFF    17408
#define PH2_SMEM  (2 * STG_BYTES)

__global__ __launch_bounds__(512)
void gat_phase2(const float* __restrict__ A)
{
    extern __shared__ unsigned char sm[];
    const uint32_t sbase0 = smem_u32(sm);

    const int t     = threadIdx.x;
    const int lane  = t & 31;
    const int wid   = t >> 5;
    const int tile  = blockIdx.x & 63;
    const int split = blockIdx.x >> 6;
    const int r0    = tile * 128;
    const int kbase = split * (N_NODES / SPLITS);
    const int NCH   = (N_NODES / SPLITS) / CH_K;   // 128

    const int m0 = (wid & 7) * 16;
    const int n0 = (wid >> 3) * 72;

    float C[9][4];
    #pragma unroll
    for (int j = 0; j < 9; j++)
        #pragma unroll
        for (int q = 0; q < 4; q++) C[j][q] = 0.0f;

    // A prefetch registers
    float4 av0, av1;
    const int ar = t >> 2;          // row 0..127
    const int ac = t & 3;           // chunk 0..3 (8 floats each)

    // ---- stage fill helpers (inlined via lambdas) ----
    auto LDG_A = [&](int i) {
        const float* src = &A[(size_t)(r0 + ar) * N_NODES + kbase + i * CH_K + ac * 8];
        av0 = reinterpret_cast<const float4*>(src)[0];
        av1 = reinterpret_cast<const float4*>(src)[1];
    };
    auto STS_A = [&](int stg) {
        __nv_bfloat162 p0 = __floats2bfloat162_rn(av0.x, av0.y);
        __nv_bfloat162 p1 = __floats2bfloat162_rn(av0.z, av0.w);
        __nv_bfloat162 p2 = __floats2bfloat162_rn(av1.x, av1.y);
        __nv_bfloat162 p3 = __floats2bfloat162_rn(av1.z, av1.w);
        uint4 u;
        u.x = *reinterpret_cast<unsigned*>(&p0);
        u.y = *reinterpret_cast<unsigned*>(&p1);
        u.z = *reinterpret_cast<unsigned*>(&p2);
        u.w = *reinterpret_cast<unsigned*>(&p3);
        *reinterpret_cast<uint4*>(sm + stg * STG_BYTES + swz(ar, ac)) = u;
    };
    auto LOAD_B = [&](int i, int stg) {
        const uint32_t db = sbase0 + stg * STG_BYTES;
        #pragma unroll
        for (int it = 0; it < 3; it++) {
            int idx = t + it * 512;
            if (idx < 1152) {
                int hl = idx >= 576;
                int j  = idx - (hl ? 576 : 0);
                int n  = j >> 2, c = j & 3;
                const __nv_bfloat16* g = (hl ? Pt_lo : Pt_hi)
                    + (size_t)n * N_NODES + kbase + i * CH_K + c * 8;
                CP_ASYNC16(db + (hl ? BL_OFF : BH_OFF) + swz(n, c), g);
            }
        }
    };

    // ---- prologue ----
    LDG_A(0);
    LOAD_B(0, 0);
    STS_A(0);
    CP_COMMIT();
    CP_WAIT0();
    __syncthreads();

    // ---- main loop ----
    for (int i = 0; i < NCH; i++) {
        const int s = i & 1;
        const bool more = (i + 1 < NCH);
        if (more) {
            LDG_A(i + 1);
            LOAD_B(i + 1, s ^ 1);
            CP_COMMIT();
        }

        // compute on stage s
        {
            const uint32_t ab = sbase0 + s * STG_BYTES;
            const uint32_t hb = ab + BH_OFF;
            const uint32_t lb = ab + BL_OFF;
            #pragma unroll
            for (int h = 0; h < 2; h++) {
                uint32_t a[4];
                {
                    int row = m0 + (lane & 15);
                    int kc  = 2 * h + (lane >> 4);
                    LDSM_X4(a, ab + swz(row, kc));
                }
                const int kcb = 2 * h + ((lane >> 3) & 1);
                #pragma unroll
                for (int jg = 0; jg < 4; jg++) {
                    int n = n0 + jg * 16 + ((lane >> 4) << 3) + (lane & 7);
                    uint32_t b[4];
                    LDSM_X4(b, hb + swz(n, kcb));
                    MMA16816(C[2*jg],   a, b[0], b[1]);
                    MMA16816(C[2*jg+1], a, b[2], b[3]);
                    LDSM_X4(b, lb + swz(n, kcb));
                    MMA16816(C[2*jg],   a, b[0], b[1]);
                    MMA16816(C[2*jg+1], a, b[2], b[3]);
                }
                {
                    int n = n0 + 64 + (lane & 7);
                    uint32_t b0, b1;
                    LDSM_X2(b0, b1, hb + swz(n, kcb));
                    MMA16816(C[8], a, b0, b1);
                    LDSM_X2(b0, b1, lb + swz(n, kcb));
                    MMA16816(C[8], a, b0, b1);
                }
            }
        }

        if (more) {
            STS_A(s ^ 1);
            CP_WAIT0();
        }
        __syncthreads();
    }

    // ---- epilogue: write fp32 partials ----
    {
        const int row1 = r0 + m0 + (lane >> 2);
        const int col0 = n0 + (lane & 3) * 2;
        float* base = &part_buf[(size_t)split * N_NODES * NCOLS];
        #pragma unroll
        for (int j = 0; j < 9; j++) {
            const int col = col0 + j * 8;
            *reinterpret_cast<float2*>(&base[(size_t)row1 * NCOLS + col]) =
                make_float2(C[j][0], C[j][1]);
            *reinterpret_cast<float2*>(&base[(size_t)(row1 + 8) * NCOLS + col]) =
                make_float2(C[j][2], C[j][3]);
        }
    }
}

// ---------------------------------------------------------------------------
// Combine: out[row][c] = relu( (p0+p1)[c] / (p0+p1)[128] )
// ---------------------------------------------------------------------------
__global__ __launch_bounds__(256)
void gat_combine(float* __restrict__ out)
{
    const int idx = blockIdx.x * 256 + threadIdx.x;
    const int row = idx >> 7;
    const int c   = idx & 127;
    const float* p0 = &part_buf[(size_t)row * NCOLS];
    const float* p1 = &part_buf[(size_t)(N_NODES + row) * NCOLS];
    const float den = p0[128] + p1[128];
    const float num = p0[c] + p1[c];
    out[idx] = fmaxf(num / den, 0.0f);
}

// ---------------------------------------------------------------------------
extern "C" void kernel_launch(void* const* d_in, const int* in_sizes, int n_in,
                              void* d_out, int out_size)
{
    const float* X   = (const float*)d_in[0];
    const float* A   = (const float*)d_in[1];
    const float* W   = (const float*)d_in[2];
    const float* a_w = (const float*)d_in[3];
    float* out = (float*)d_out;

    cudaFuncSetAttribute(gat_phase2,
                         cudaFuncAttributeMaxDynamicSharedMemorySize, PH2_SMEM);

    gat_phase1<<<N_NODES / 32, 256>>>(X, W, a_w);
    gat_phase2<<<64 * SPLITS, 512, PH2_SMEM>>>(A);
    gat_combine<<<(N_NODES * OUT_DIM) / 256, 256>>>(out);
}

// round 5
// speedup vs baseline: 3.8856x; 1.5837x over previous
#include <cuda_runtime.h>
#include <cuda_bf16.h>
#include <cstdint>

#define N_NODES 8192
#define IN_DIM  256
#define OUT_DIM 128
#define NCOLS   144     // 128 out cols + g col (idx 128) + 15 pad
#define CH_K    32      // K per chunk (bf16)
#define SPLITS  4

// ---------------- device scratch (zero-initialized at module load) ---------
__device__ __align__(16) __nv_bfloat16 Pt_hi[NCOLS * N_NODES];  // [n][k]
__device__ __align__(16) __nv_bfloat16 Pt_lo[NCOLS * N_NODES];  // [n][k]
__device__ __align__(16) float part_buf[SPLITS * N_NODES * NCOLS];

// ---------------- helpers ---------------------------------------------------
__device__ __forceinline__ uint32_t smem_u32(const void* p) {
    uint32_t a;
    asm("{ .reg .u64 t; cvta.to.shared.u64 t, %1; cvt.u32.u64 %0, t; }"
        : "=r"(a) : "l"(p));
    return a;
}
// XOR-swizzled byte offset inside a [rows][32 bf16] tile (64B rows)
__device__ __forceinline__ uint32_t swz(int row, int chunk) {
    return (uint32_t)(row * 64 + ((chunk ^ ((row >> 1) & 3)) << 4));
}

#define LDSM_X4(r, addr) \
    asm volatile("ldmatrix.sync.aligned.m8n8.x4.shared.b16 {%0,%1,%2,%3}, [%4];" \
        : "=r"((r)[0]), "=r"((r)[1]), "=r"((r)[2]), "=r"((r)[3]) : "r"(addr))
#define LDSM_X2(r0, r1, addr) \
    asm volatile("ldmatrix.sync.aligned.m8n8.x2.shared.b16 {%0,%1}, [%2];" \
        : "=r"(r0), "=r"(r1) : "r"(addr))
#define MMA16816(c, a, b0, b1) \
    asm volatile("mma.sync.aligned.m16n8k16.row.col.f32.bf16.bf16.f32 " \
        "{%0,%1,%2,%3},{%4,%5,%6,%7},{%8,%9},{%0,%1,%2,%3};" \
        : "+f"((c)[0]), "+f"((c)[1]), "+f"((c)[2]), "+f"((c)[3]) \
        : "r"((a)[0]), "r"((a)[1]), "r"((a)[2]), "r"((a)[3]), "r"(b0), "r"(b1))
#define CP_ASYNC16(daddr, gptr) \
    asm volatile("cp.async.cg.shared.global [%0], [%1], 16;" \
        :: "r"(daddr), "l"(gptr) : "memory")
#define CP_COMMIT() asm volatile("cp.async.commit_group;" ::: "memory")
#define CP_WAIT0()  asm volatile("cp.async.wait_group 0;" ::: "memory")
#define CP_WAIT1()  asm volatile("cp.async.wait_group 1;" ::: "memory")

// ---------------------------------------------------------------------------
// Phase 1: Wh = X @ W^T, e = relu(Wh)@a_w, g = exp(e).
// Writes Pt_hi/Pt_lo[n][j]: n<128 = bf16 hi/lo split of g[j]*Wh[j][n],
// n=128 = hi/lo of g[j]. Rows 129..143 stay zero.
// 256 blocks x 32 nodes, 256 threads, thread tile 2 rows x 8 consecutive cols.
// ---------------------------------------------------------------------------
__global__ __launch_bounds__(256)
void gat_phase1(const float* __restrict__ X,
                const float* __restrict__ W,
                const float* __restrict__ a_w)
{
    __shared__ __align__(16) unsigned char sraw[21504];
    __shared__ float aw_s[OUT_DIM];
    float* Xs = (float*)sraw;             // [32][36]
    float* Ws = (float*)(sraw + 4608);    // [32][132]

    const int t  = threadIdx.x;
    const int tx = t & 15;
    const int ty = t >> 4;
    const int node0 = blockIdx.x * 32;

    if (t < OUT_DIM) aw_s[t] = a_w[t];

    float acc[2][8];
    #pragma unroll
    for (int r = 0; r < 2; r++)
        #pragma unroll
        for (int j = 0; j < 8; j++) acc[r][j] = 0.0f;

    for (int k0 = 0; k0 < IN_DIM; k0 += 32) {
        {   // X tile: 32 rows x 32 k (transposed into smem)
            const int row = t >> 3, q = t & 7;
            float4 v = *reinterpret_cast<const float4*>(
                &X[(node0 + row) * IN_DIM + k0 + 4 * q]);
            Xs[(4*q+0)*36 + row] = v.x; Xs[(4*q+1)*36 + row] = v.y;
            Xs[(4*q+2)*36 + row] = v.z; Xs[(4*q+3)*36 + row] = v.w;
        }
        {   // W tile transposed: Ws[k][c] = W[c][k0+k], float4 global reads
            const int q = t & 7, cb = t >> 3;   // q: k-quad, cb: 0..31
            #pragma unroll
            for (int it = 0; it < 4; it++) {
                const int c = cb + 32 * it;
                float4 v = *reinterpret_cast<const float4*>(
                    &W[c * IN_DIM + k0 + 4 * q]);
                Ws[(4*q+0)*132 + c] = v.x; Ws[(4*q+1)*132 + c] = v.y;
                Ws[(4*q+2)*132 + c] = v.z; Ws[(4*q+3)*132 + c] = v.w;
            }
        }
        __syncthreads();

        #pragma unroll
        for (int k = 0; k < 32; k++) {
            float2 av = *reinterpret_cast<const float2*>(&Xs[k * 36 + 2 * ty]);
            float4 b0 = *reinterpret_cast<const float4*>(&Ws[k * 132 + 8 * tx]);
            float4 b1 = *reinterpret_cast<const float4*>(&Ws[k * 132 + 8 * tx + 4]);
            float b[8] = {b0.x, b0.y, b0.z, b0.w, b1.x, b1.y, b1.z, b1.w};
            #pragma unroll
            for (int j = 0; j < 8; j++) {
                acc[0][j] = fmaf(av.x, b[j], acc[0][j]);
                acc[1][j] = fmaf(av.y, b[j], acc[1][j]);
            }
        }
        __syncthreads();
    }

    float g[2];
    #pragma unroll
    for (int r = 0; r < 2; r++) {
        float ep = 0.0f;
        #pragma unroll
        for (int j = 0; j < 8; j++)
            ep = fmaf(fmaxf(acc[r][j], 0.0f), aw_s[8 * tx + j], ep);
        #pragma unroll
        for (int m = 8; m >= 1; m >>= 1)
            ep += __shfl_xor_sync(0xffffffffu, ep, m, 16);
        g[r] = expf(ep);
    }

    // transpose + split through smem, two passes (hi then lo)
    __nv_bfloat16* th = (__nv_bfloat16*)sraw;   // [129][36]
    #pragma unroll
    for (int pass = 0; pass < 2; pass++) {
        __nv_bfloat16* dstbuf = pass ? Pt_lo : Pt_hi;
        #pragma unroll
        for (int j = 0; j < 8; j++) {
            const int c = 8 * tx + j;
            float v0 = g[0] * acc[0][j];
            float v1 = g[1] * acc[1][j];
            __nv_bfloat16 h0 = __float2bfloat16(v0);
            __nv_bfloat16 h1 = __float2bfloat16(v1);
            __nv_bfloat162 o;
            if (pass == 0) o = __halves2bfloat162(h0, h1);
            else o = __halves2bfloat162(
                         __float2bfloat16(v0 - __bfloat162float(h0)),
                         __float2bfloat16(v1 - __bfloat162float(h1)));
            *reinterpret_cast<__nv_bfloat162*>(&th[c * 36 + 2 * ty]) = o;
        }
        if (tx == 0) {  // g column (row 128)
            __nv_bfloat16 h0 = __float2bfloat16(g[0]);
            __nv_bfloat16 h1 = __float2bfloat16(g[1]);
            __nv_bfloat162 o;
            if (pass == 0) o = __halves2bfloat162(h0, h1);
            else o = __halves2bfloat162(
                         __float2bfloat16(g[0] - __bfloat162float(h0)),
                         __float2bfloat16(g[1] - __bfloat162float(h1)));
            *reinterpret_cast<__nv_bfloat162*>(&th[128 * 36 + 2 * ty]) = o;
        }
        __syncthreads();
        {
            const int wid = t >> 5, lid = t & 31;
            const int l = lid & 15;
            for (int c = wid * 2 + (lid >> 4); c < 129; c += 16) {
                unsigned v = *reinterpret_cast<unsigned*>(&th[c * 36 + 2 * l]);
                *reinterpret_cast<unsigned*>(
                    &dstbuf[(size_t)c * N_NODES + node0 + 2 * l]) = v;
            }
        }
        __syncthreads();
    }
}

// ---------------------------------------------------------------------------
// Phase 2: HMMA bf16 split GEMM.
// CTA: M=128, N=144, K-chunk 32; 256 threads = 8 warps (4m x 2n, m32 x n72).
// 3-stage pipeline. 256 CTAs (64 M-tiles x 4 K-splits), 2 CTAs/SM.
// ---------------------------------------------------------------------------
#define STG_BYTES 26624     // A 8192 + Bhi 9216 + Blo 9216
#define BH_OFF    8192
#define BL_OFF    17408
#define PH2_SMEM  (3 * STG_BYTES)

__global__ __launch_bounds__(256, 2)
void gat_phase2(const float* __restrict__ A)
{
    extern __shared__ unsigned char sm[];
    const uint32_t sbase0 = smem_u32(sm);

    const int t     = threadIdx.x;
    const int lane  = t & 31;
    const int wid   = t >> 5;
    const int tile  = blockIdx.x & 63;
    const int split = blockIdx.x >> 6;
    const int r0    = tile * 128;
    const int kbase = split * (N_NODES / SPLITS);
    const int NCH   = (N_NODES / SPLITS) / CH_K;   // 64

    const int m0 = (wid & 3) * 32;
    const int n0 = (wid >> 2) * 72;

    float C0[9][4], C1[9][4];
    #pragma unroll
    for (int j = 0; j < 9; j++)
        #pragma unroll
        for (int q = 0; q < 4; q++) { C0[j][q] = 0.0f; C1[j][q] = 0.0f; }

    // A prefetch registers: each thread owns 16 consecutive floats of one row
    float4 av[4];
    const int ar = t >> 1;            // row 0..127
    const int ac = t & 1;             // half (16 floats)

    auto LDG_A = [&](int i) {
        const float4* src = reinterpret_cast<const float4*>(
            &A[(size_t)(r0 + ar) * N_NODES + kbase + i * CH_K + ac * 16]);
        av[0] = src[0]; av[1] = src[1]; av[2] = src[2]; av[3] = src[3];
    };
    auto STS_A = [&](int stg) {
        #pragma unroll
        for (int h = 0; h < 2; h++) {
            __nv_bfloat162 p0 = __floats2bfloat162_rn(av[2*h].x, av[2*h].y);
            __nv_bfloat162 p1 = __floats2bfloat162_rn(av[2*h].z, av[2*h].w);
            __nv_bfloat162 p2 = __floats2bfloat162_rn(av[2*h+1].x, av[2*h+1].y);
            __nv_bfloat162 p3 = __floats2bfloat162_rn(av[2*h+1].z, av[2*h+1].w);
            uint4 u;
            u.x = *reinterpret_cast<unsigned*>(&p0);
            u.y = *reinterpret_cast<unsigned*>(&p1);
            u.z = *reinterpret_cast<unsigned*>(&p2);
            u.w = *reinterpret_cast<unsigned*>(&p3);
            *reinterpret_cast<uint4*>(sm + stg * STG_BYTES + swz(ar, ac * 2 + h)) = u;
        }
    };
    auto LOAD_B = [&](int i, int stg) {
        const uint32_t db = sbase0 + stg * STG_BYTES;
        #pragma unroll
        for (int it = 0; it < 5; it++) {
            int idx = t + it * 256;
            if (idx < 1152) {
                int hl = idx >= 576;
                int j  = idx - (hl ? 576 : 0);
                int n  = j >> 2, c = j & 3;
                const __nv_bfloat16* g = (hl ? Pt_lo : Pt_hi)
                    + (size_t)n * N_NODES + kbase + i * CH_K + c * 8;
                CP_ASYNC16(db + (hl ? BL_OFF : BH_OFF) + swz(n, c), g);
            }
        }
    };

    // ---- prologue: fill stages 0 and 1 ----
    LDG_A(0); STS_A(0); LOAD_B(0, 0); CP_COMMIT();
    LDG_A(1); STS_A(1); LOAD_B(1, 1); CP_COMMIT();
    CP_WAIT1();
    __syncthreads();

    // ---- main loop ----
    for (int i = 0; i < NCH; i++) {
        const int s = i % 3;
        const bool more2 = (i + 2 < NCH);
        const int s2 = (i + 2) % 3;
        if (more2) {
            LDG_A(i + 2);
            LOAD_B(i + 2, s2);
            CP_COMMIT();
        }

        // compute on stage s
        {
            const uint32_t ab = sbase0 + s * STG_BYTES;
            const uint32_t hb = ab + BH_OFF;
            const uint32_t lb = ab + BL_OFF;
            #pragma unroll
            for (int h = 0; h < 2; h++) {
                uint32_t a0[4], a1[4];
                {
                    const int kc = 2 * h + (lane >> 4);
                    LDSM_X4(a0, ab + swz(m0 + (lane & 15), kc));
                    LDSM_X4(a1, ab + swz(m0 + 16 + (lane & 15), kc));
                }
                const int kcb = 2 * h + ((lane >> 3) & 1);
                #pragma unroll
                for (int pl = 0; pl < 2; pl++) {
                    const uint32_t pb = pl ? lb : hb;
                    #pragma unroll
                    for (int jg = 0; jg < 4; jg++) {
                        int n = n0 + jg * 16 + ((lane >> 4) << 3) + (lane & 7);
                        uint32_t b[4];
                        LDSM_X4(b, pb + swz(n, kcb));
                        MMA16816(C0[2*jg],   a0, b[0], b[1]);
                        MMA16816(C0[2*jg+1], a0, b[2], b[3]);
                        MMA16816(C1[2*jg],   a1, b[0], b[1]);
                        MMA16816(C1[2*jg+1], a1, b[2], b[3]);
                    }
                    {
                        int n = n0 + 64 + (lane & 7);
                        uint32_t b0, b1;
                        LDSM_X2(b0, b1, pb + swz(n, kcb));
                        MMA16816(C0[8], a0, b0, b1);
                        MMA16816(C1[8], a1, b0, b1);
                    }
                }
            }
        }

        if (more2) {
            STS_A(s2);
            CP_WAIT1();
        } else {
            CP_WAIT0();
        }
        __syncthreads();
    }

    // ---- epilogue: write fp32 partials ----
    {
        const int rowb = r0 + m0 + (lane >> 2);
        const int col0 = n0 + (lane & 3) * 2;
        float* base = &part_buf[(size_t)split * N_NODES * NCOLS];
        #pragma unroll
        for (int j = 0; j < 9; j++) {
            const int col = col0 + j * 8;
            *reinterpret_cast<float2*>(&base[(size_t)rowb * NCOLS + col]) =
                make_float2(C0[j][0], C0[j][1]);
            *reinterpret_cast<float2*>(&base[(size_t)(rowb + 8) * NCOLS + col]) =
                make_float2(C0[j][2], C0[j][3]);
            *reinterpret_cast<float2*>(&base[(size_t)(rowb + 16) * NCOLS + col]) =
                make_float2(C1[j][0], C1[j][1]);
            *reinterpret_cast<float2*>(&base[(size_t)(rowb + 24) * NCOLS + col]) =
                make_float2(C1[j][2], C1[j][3]);
        }
    }
}

// ---------------------------------------------------------------------------
// Combine: out[row][c] = relu( (Σ_s p_s)[c] / (Σ_s p_s)[128] )
// ---------------------------------------------------------------------------
__global__ __launch_bounds__(256)
void gat_combine(float* __restrict__ out)
{
    const int idx = blockIdx.x * 256 + threadIdx.x;
    const int row = idx >> 7;
    const int c   = idx & 127;
    float num = 0.0f, den = 0.0f;
    #pragma unroll
    for (int s = 0; s < SPLITS; s++) {
        const float* p = &part_buf[((size_t)s * N_NODES + row) * NCOLS];
        num += p[c];
        den += p[128];
    }
    out[idx] = fmaxf(num / den, 0.0f);
}

// ---------------------------------------------------------------------------
extern "C" void kernel_launch(void* const* d_in, const int* in_sizes, int n_in,
                              void* d_out, int out_size)
{
    const float* X   = (const float*)d_in[0];
    const float* A   = (const float*)d_in[1];
    const float* W   = (const float*)d_in[2];
    const float* a_w = (const float*)d_in[3];
    float* out = (float*)d_out;

    cudaFuncSetAttribute(gat_phase2,
                         cudaFuncAttributeMaxDynamicSharedMemorySize, PH2_SMEM);

    gat_phase1<<<N_NODES / 32, 256>>>(X, W, a_w);
    gat_phase2<<<64 * SPLITS, 256, PH2_SMEM>>>(A);
    gat_combine<<<(N_NODES * OUT_DIM) / 256, 256>>>(out);
}

// round 6
// speedup vs baseline: 3.8909x; 1.0014x over previous
#include <cuda_runtime.h>
#include <cuda_fp16.h>
#include <cstdint>

#define N_NODES 8192
#define IN_DIM  256
#define OUT_DIM 128
#define NCOLS   144     // 128 out cols + g col (idx 128) + 15 pad
#define CH_K    32
#define SPLITS  4

// ---------------- device scratch (zero-initialized at module load) ---------
__device__ __align__(16) __half Pt_f16[NCOLS * N_NODES];      // [n][k], rows>128 stay 0
__device__ __align__(16) float  Wh_buf[N_NODES * OUT_DIM];    // fp32 Wh
__device__ __align__(16) float  e_buf[N_NODES];
__device__ unsigned emax_enc;                                  // monotone-encoded max e
__device__ __align__(16) float part_buf[SPLITS * N_NODES * NCOLS];

// ---------------- helpers ---------------------------------------------------
__device__ __forceinline__ uint32_t smem_u32(const void* p) {
    uint32_t a;
    asm("{ .reg .u64 t; cvta.to.shared.u64 t, %1; cvt.u32.u64 %0, t; }"
        : "=r"(a) : "l"(p));
    return a;
}
__device__ __forceinline__ unsigned fenc(float f) {           // monotone float->uint
    unsigned u = __float_as_uint(f);
    return u ^ ((unsigned)((int)u >> 31) | 0x80000000u);
}
__device__ __forceinline__ float fdec(unsigned v) {
    unsigned u = (v & 0x80000000u) ? (v ^ 0x80000000u) : ~v;
    return __uint_as_float(u);
}
// XOR-swizzled byte offset inside a [rows][32 halves] tile (64B rows)
__device__ __forceinline__ uint32_t swz(int row, int chunk) {
    return (uint32_t)(row * 64 + ((chunk ^ ((row >> 1) & 3)) << 4));
}

#define LDSM_X4(r, addr) \
    asm volatile("ldmatrix.sync.aligned.m8n8.x4.shared.b16 {%0,%1,%2,%3}, [%4];" \
        : "=r"((r)[0]), "=r"((r)[1]), "=r"((r)[2]), "=r"((r)[3]) : "r"(addr))
#define LDSM_X2(r0, r1, addr) \
    asm volatile("ldmatrix.sync.aligned.m8n8.x2.shared.b16 {%0,%1}, [%2];" \
        : "=r"(r0), "=r"(r1) : "r"(addr))
#define MMA16816(c, a, b0, b1) \
    asm volatile("mma.sync.aligned.m16n8k16.row.col.f32.f16.f16.f32 " \
        "{%0,%1,%2,%3},{%4,%5,%6,%7},{%8,%9},{%0,%1,%2,%3};" \
        : "+f"((c)[0]), "+f"((c)[1]), "+f"((c)[2]), "+f"((c)[3]) \
        : "r"((a)[0]), "r"((a)[1]), "r"((a)[2]), "r"((a)[3]), "r"(b0), "r"(b1))
#define CP_ASYNC16(daddr, gptr) \
    asm volatile("cp.async.cg.shared.global [%0], [%1], 16;" \
        :: "r"(daddr), "l"(gptr) : "memory")
#define CP_COMMIT() asm volatile("cp.async.commit_group;" ::: "memory")
#define CP_WAIT0()  asm volatile("cp.async.wait_group 0;" ::: "memory")
#define CP_WAIT1()  asm volatile("cp.async.wait_group 1;" ::: "memory")

// ---------------------------------------------------------------------------
// Phase 1: Wh = X @ W^T (fp32 -> Wh_buf), e = relu(Wh)@a_w -> e_buf,
// fused global max of e via atomicMax. 512 blocks x 16 nodes, 256 threads,
// thread tile 1 row x 8 consecutive cols.
// ---------------------------------------------------------------------------
__global__ __launch_bounds__(256)
void gat_phase1(const float* __restrict__ X,
                const float* __restrict__ W,
                const float* __restrict__ a_w)
{
    __shared__ float Xs[32 * 20];     // [k][row], pad 20
    __shared__ float Ws[32 * 132];    // [k][c]
    __shared__ float aw_s[OUT_DIM];

    const int t  = threadIdx.x;
    const int tx = t & 15;
    const int ty = t >> 4;
    const int node0 = blockIdx.x * 16;

    if (t < OUT_DIM) aw_s[t] = a_w[t];

    float acc[8];
    #pragma unroll
    for (int j = 0; j < 8; j++) acc[j] = 0.0f;

    for (int k0 = 0; k0 < IN_DIM; k0 += 32) {
        if (t < 128) {   // X tile: 16 rows x 32 k (transposed)
            const int row = t >> 3, q = t & 7;
            float4 v = *reinterpret_cast<const float4*>(
                &X[(node0 + row) * IN_DIM + k0 + 4 * q]);
            Xs[(4*q+0)*20 + row] = v.x; Xs[(4*q+1)*20 + row] = v.y;
            Xs[(4*q+2)*20 + row] = v.z; Xs[(4*q+3)*20 + row] = v.w;
        }
        {   // W tile transposed: Ws[k][c] = W[c][k0+k]
            const int q = t & 7, cb = t >> 3;
            #pragma unroll
            for (int it = 0; it < 4; it++) {
                const int c = cb + 32 * it;
                float4 v = *reinterpret_cast<const float4*>(
                    &W[c * IN_DIM + k0 + 4 * q]);
                Ws[(4*q+0)*132 + c] = v.x; Ws[(4*q+1)*132 + c] = v.y;
                Ws[(4*q+2)*132 + c] = v.z; Ws[(4*q+3)*132 + c] = v.w;
            }
        }
        __syncthreads();

        #pragma unroll
        for (int k = 0; k < 32; k++) {
            float a = Xs[k * 20 + ty];
            float4 b0 = *reinterpret_cast<const float4*>(&Ws[k * 132 + 8 * tx]);
            float4 b1 = *reinterpret_cast<const float4*>(&Ws[k * 132 + 8 * tx + 4]);
            acc[0] = fmaf(a, b0.x, acc[0]); acc[1] = fmaf(a, b0.y, acc[1]);
            acc[2] = fmaf(a, b0.z, acc[2]); acc[3] = fmaf(a, b0.w, acc[3]);
            acc[4] = fmaf(a, b1.x, acc[4]); acc[5] = fmaf(a, b1.y, acc[5]);
            acc[6] = fmaf(a, b1.z, acc[6]); acc[7] = fmaf(a, b1.w, acc[7]);
        }
        __syncthreads();
    }

    // e = relu(Wh) @ a_w, reduced over the 16 tx lanes
    float ep = 0.0f;
    #pragma unroll
    for (int j = 0; j < 8; j++)
        ep = fmaf(fmaxf(acc[j], 0.0f), aw_s[8 * tx + j], ep);
    #pragma unroll
    for (int m = 8; m >= 1; m >>= 1)
        ep += __shfl_xor_sync(0xffffffffu, ep, m, 16);

    const int row = node0 + ty;
    *reinterpret_cast<float4*>(&Wh_buf[row * OUT_DIM + 8 * tx]) =
        make_float4(acc[0], acc[1], acc[2], acc[3]);
    *reinterpret_cast<float4*>(&Wh_buf[row * OUT_DIM + 8 * tx + 4]) =
        make_float4(acc[4], acc[5], acc[6], acc[7]);
    if (tx == 0) {
        e_buf[row] = ep;
        atomicMax(&emax_enc, fenc(ep));
    }
}

// ---------------------------------------------------------------------------
// Scale: g[j] = exp(e[j]-emax); Pt_f16[c][j] = fp16( c<128 ? g*Wh[j][c] : g ).
// grid 516 x 256 threads; each thread writes 8 consecutive nodes of one row.
// ---------------------------------------------------------------------------
__global__ __launch_bounds__(256)
void gat_scale()
{
    const int gi = blockIdx.x * 256 + threadIdx.x;   // 0..132095
    if (gi >= 129 * (N_NODES / 8)) return;
    const int c    = gi >> 10;            // 0..128
    const int node = (gi & 1023) * 8;
    const float emax = fdec(emax_enc);

    __half h[8];
    #pragma unroll
    for (int u = 0; u < 8; u++) {
        const float g = expf(e_buf[node + u] - emax);
        const float v = (c == 128) ? g : g * Wh_buf[(node + u) * OUT_DIM + c];
        h[u] = __float2half_rn(v);
    }
    *reinterpret_cast<uint4*>(&Pt_f16[(size_t)c * N_NODES + node]) =
        *reinterpret_cast<uint4*>(h);
}

// ---------------------------------------------------------------------------
// Phase 2: fp16 HMMA GEMM. part[split] = A_f16[128 x 2048] @ Pt^T
// CTA: M=128, N=144, K-chunk 32; 256 threads = 8 warps (4m x 2n, m32 x n72).
// 3-stage pipeline, 256 CTAs (64 M-tiles x 4 K-splits), 2 CTAs/SM.
// ---------------------------------------------------------------------------
#define STG_BYTES 17408     // A 8192 + B 9216
#define B_OFF     8192
#define PH2_SMEM  (3 * STG_BYTES)

__global__ __launch_bounds__(256, 2)
void gat_phase2(const float* __restrict__ A)
{
    extern __shared__ unsigned char sm[];
    const uint32_t sbase0 = smem_u32(sm);

    const int t     = threadIdx.x;
    const int lane  = t & 31;
    const int wid   = t >> 5;
    const int tile  = blockIdx.x & 63;
    const int split = blockIdx.x >> 6;
    const int r0    = tile * 128;
    const int kbase = split * (N_NODES / SPLITS);
    const int NCH   = (N_NODES / SPLITS) / CH_K;   // 64

    const int m0 = (wid & 3) * 32;
    const int n0 = (wid >> 2) * 72;

    float C0[9][4], C1[9][4];
    #pragma unroll
    for (int j = 0; j < 9; j++)
        #pragma unroll
        for (int q = 0; q < 4; q++) { C0[j][q] = 0.0f; C1[j][q] = 0.0f; }

    float4 av[4];
    const int ar = t >> 1;
    const int ac = t & 1;

    auto LDG_A = [&](int i) {
        const float4* src = reinterpret_cast<const float4*>(
            &A[(size_t)(r0 + ar) * N_NODES + kbase + i * CH_K + ac * 16]);
        av[0] = src[0]; av[1] = src[1]; av[2] = src[2]; av[3] = src[3];
    };
    auto STS_A = [&](int stg) {
        #pragma unroll
        for (int h = 0; h < 2; h++) {
            __half2 p0 = __floats2half2_rn(av[2*h].x, av[2*h].y);
            __half2 p1 = __floats2half2_rn(av[2*h].z, av[2*h].w);
            __half2 p2 = __floats2half2_rn(av[2*h+1].x, av[2*h+1].y);
            __half2 p3 = __floats2half2_rn(av[2*h+1].z, av[2*h+1].w);
            uint4 u;
            u.x = *reinterpret_cast<unsigned*>(&p0);
            u.y = *reinterpret_cast<unsigned*>(&p1);
            u.z = *reinterpret_cast<unsigned*>(&p2);
            u.w = *reinterpret_cast<unsigned*>(&p3);
            *reinterpret_cast<uint4*>(sm + stg * STG_BYTES + swz(ar, ac * 2 + h)) = u;
        }
    };
    auto LOAD_B = [&](int i, int stg) {
        const uint32_t db = sbase0 + stg * STG_BYTES + B_OFF;
        #pragma unroll
        for (int it = 0; it < 3; it++) {
            int idx = t + it * 256;
            if (idx < 576) {
                int n = idx >> 2, c = idx & 3;
                const __half* g = Pt_f16 + (size_t)n * N_NODES
                                + kbase + i * CH_K + c * 8;
                CP_ASYNC16(db + swz(n, c), g);
            }
        }
    };

    // ---- prologue ----
    LDG_A(0); STS_A(0); LOAD_B(0, 0); CP_COMMIT();
    LDG_A(1); STS_A(1); LOAD_B(1, 1); CP_COMMIT();
    CP_WAIT1();
    __syncthreads();

    // ---- main loop ----
    for (int i = 0; i < NCH; i++) {
        const int s = i % 3;
        const bool more2 = (i + 2 < NCH);
        const int s2 = (i + 2) % 3;
        if (more2) {
            LDG_A(i + 2);
            LOAD_B(i + 2, s2);
            CP_COMMIT();
        }

        {
            const uint32_t ab = sbase0 + s * STG_BYTES;
            const uint32_t bb = ab + B_OFF;
            #pragma unroll
            for (int h = 0; h < 2; h++) {
                uint32_t a0[4], a1[4];
                {
                    const int kc = 2 * h + (lane >> 4);
                    LDSM_X4(a0, ab + swz(m0 + (lane & 15), kc));
                    LDSM_X4(a1, ab + swz(m0 + 16 + (lane & 15), kc));
                }
                const int kcb = 2 * h + ((lane >> 3) & 1);
                #pragma unroll
                for (int jg = 0; jg < 4; jg++) {
                    int n = n0 + jg * 16 + ((lane >> 4) << 3) + (lane & 7);
                    uint32_t b[4];
                    LDSM_X4(b, bb + swz(n, kcb));
                    MMA16816(C0[2*jg],   a0, b[0], b[1]);
                    MMA16816(C0[2*jg+1], a0, b[2], b[3]);
                    MMA16816(C1[2*jg],   a1, b[0], b[1]);
                    MMA16816(C1[2*jg+1], a1, b[2], b[3]);
                }
                {
                    int n = n0 + 64 + (lane & 7);
                    uint32_t b0, b1;
                    LDSM_X2(b0, b1, bb + swz(n, kcb));
                    MMA16816(C0[8], a0, b0, b1);
                    MMA16816(C1[8], a1, b0, b1);
                }
            }
        }

        if (more2) {
            STS_A(s2);
            CP_WAIT1();
        } else {
            CP_WAIT0();
        }
        __syncthreads();
    }

    // ---- epilogue: fp32 partials ----
    {
        const int rowb = r0 + m0 + (lane >> 2);
        const int col0 = n0 + (lane & 3) * 2;
        float* base = &part_buf[(size_t)split * N_NODES * NCOLS];
        #pragma unroll
        for (int j = 0; j < 9; j++) {
            const int col = col0 + j * 8;
            *reinterpret_cast<float2*>(&base[(size_t)rowb * NCOLS + col]) =
                make_float2(C0[j][0], C0[j][1]);
            *reinterpret_cast<float2*>(&base[(size_t)(rowb + 8) * NCOLS + col]) =
                make_float2(C0[j][2], C0[j][3]);
            *reinterpret_cast<float2*>(&base[(size_t)(rowb + 16) * NCOLS + col]) =
                make_float2(C1[j][0], C1[j][1]);
            *reinterpret_cast<float2*>(&base[(size_t)(rowb + 24) * NCOLS + col]) =
                make_float2(C1[j][2], C1[j][3]);
        }
    }
}

// ---------------------------------------------------------------------------
// Combine: out[row][c] = relu( (Σ_s p_s)[c] / (Σ_s p_s)[128] )
// ---------------------------------------------------------------------------
__global__ __launch_bounds__(256)
void gat_combine(float* __restrict__ out)
{
    const int idx = blockIdx.x * 256 + threadIdx.x;
    const int row = idx >> 7;
    const int c   = idx & 127;
    float num = 0.0f, den = 0.0f;
    #pragma unroll
    for (int s = 0; s < SPLITS; s++) {
        const float* p = &part_buf[((size_t)s * N_NODES + row) * NCOLS];
        num += p[c];
        den += p[128];
    }
    out[idx] = fmaxf(num / den, 0.0f);
}

// ---------------------------------------------------------------------------
extern "C" void kernel_launch(void* const* d_in, const int* in_sizes, int n_in,
                              void* d_out, int out_size)
{
    const float* X   = (const float*)d_in[0];
    const float* A   = (const float*)d_in[1];
    const float* W   = (const float*)d_in[2];
    const float* a_w = (const float*)d_in[3];
    float* out = (float*)d_out;

    cudaFuncSetAttribute(gat_phase2,
                         cudaFuncAttributeMaxDynamicSharedMemorySize, PH2_SMEM);

    gat_phase1<<<N_NODES / 16, 256>>>(X, W, a_w);
    gat_scale<<<516, 256>>>();
    gat_phase2<<<64 * SPLITS, 256, PH2_SMEM>>>(A);
    gat_combine<<<(N_NODES * OUT_DIM) / 256, 256>>>(out);
}